// round 11
// baseline (speedup 1.0000x reference)
#include <cuda_runtime.h>
#include <cuda_fp16.h>
#include <cstdint>

#define N_TOK 262144
#define NCH   64

__device__ float  g_S [2 * 4096];
__device__ float  g_M [2 * 4096];    // M: [o][c]
__device__ __half g_Mh[2 * 4096];    // mean-free M' in f16
__device__ float  g_Bp[64];          // mean-free bias b'
__device__ __half g_xh[(size_t)2 * NCH * N_TOK];   // f16 x cache (64MB)

// ---------------------------------------------------------------------------
static __device__ __forceinline__ uint32_t smem_u32(const void* p) {
    uint32_t a;
    asm("{ .reg .u64 t; cvta.to.shared.u64 t, %1; cvt.u32.u64 %0, t; }" : "=r"(a) : "l"(p));
    return a;
}
static __device__ __forceinline__ void ldsm4(uint32_t (&r)[4], uint32_t a) {
    asm volatile("ldmatrix.sync.aligned.m8n8.x4.shared.b16 {%0,%1,%2,%3}, [%4];"
                 : "=r"(r[0]), "=r"(r[1]), "=r"(r[2]), "=r"(r[3]) : "r"(a));
}
static __device__ __forceinline__ void ldsm4t(uint32_t (&r)[4], uint32_t a) {
    asm volatile("ldmatrix.sync.aligned.m8n8.x4.trans.shared.b16 {%0,%1,%2,%3}, [%4];"
                 : "=r"(r[0]), "=r"(r[1]), "=r"(r[2]), "=r"(r[3]) : "r"(a));
}
static __device__ __forceinline__ void mma16816(float (&d)[4], const uint32_t (&a)[4],
                                                uint32_t b0, uint32_t b1) {
    asm volatile("mma.sync.aligned.m16n8k16.row.col.f32.f16.f16.f32 "
                 "{%0,%1,%2,%3},{%4,%5,%6,%7},{%8,%9},{%0,%1,%2,%3};"
                 : "+f"(d[0]), "+f"(d[1]), "+f"(d[2]), "+f"(d[3])
                 : "r"(a[0]), "r"(a[1]), "r"(a[2]), "r"(a[3]), "r"(b0), "r"(b1));
}
static __device__ __forceinline__ uint32_t cvt2h(float lo, float hi) {
    uint32_t d;
    asm("cvt.rn.f16x2.f32 %0,%1,%2;" : "=r"(d) : "f"(hi), "f"(lo));
    return d;
}
static __device__ __forceinline__ void stcs2(float* p, float a, float b) {
    asm volatile("st.global.cs.v2.f32 [%0], {%1,%2};" :: "l"(p), "f"(a), "f"(b) : "memory");
}

// ---------------------------------------------------------------------------
__global__ void zero_kernel() {
    int i = blockIdx.x * 256 + threadIdx.x;
    if (i < 2 * 4096) { g_S[i] = 0.0f; g_M[i] = 0.0f; }
}

// ---------------------------------------------------------------------------
// Pass A: S = X16·X16^T, and write f16 x to g_xh.
// 128-tok tiles; LDG.128 reg pipeline (1 tile ahead), double-buffered f16
// smem tile [64 ch][272B], mma runs one tile behind -> ONE sync per tile.
// Warp = (m-stripe mw, token-half kh); D[16][64] in regs across all tiles.
// ---------------------------------------------------------------------------
#define GRAM_SMEM 34816

__global__ void __launch_bounds__(256, 2) gram_kernel(const float* __restrict__ x) {
    extern __shared__ char smem[];
    const uint32_t sb = smem_u32(smem);
    const int tid = threadIdx.x, wid = tid >> 5, lane = tid & 31;
    const int b = blockIdx.y;
    const float* xb = x + (size_t)b * NCH * N_TOK;
    __half* xhb = g_xh + (size_t)b * NCH * N_TOK;
    const int mw = wid & 3, kh = wid >> 2;
    const int NT = N_TOK / 128, S = gridDim.x, bx = blockIdx.x;
    const int n = (NT - 1 - bx) / S + 1;

    float d[8][4];
#pragma unroll
    for (int nn = 0; nn < 8; nn++)
#pragma unroll
        for (int r = 0; r < 4; r++) d[nn][r] = 0.0f;

    const int c0 = (tid >> 4) * 4;
    const int t8 = (tid & 15) * 8;
    const uint32_t aOff = (16 * mw + (lane & 15)) * 272 + ((lane >> 4) & 1) * 16 + kh * 128;
    const uint32_t bOff = (lane & 15) * 272 + ((lane >> 4) & 1) * 16 + kh * 128;

    // prologue: LDG tile 0
    float4 v[4][2];
#pragma unroll
    for (int cc = 0; cc < 4; cc++) {
        const float* p = xb + (size_t)(c0 + cc) * N_TOK + bx * 128 + t8;
        v[cc][0] = *reinterpret_cast<const float4*>(p);
        v[cc][1] = *reinterpret_cast<const float4*>(p + 4);
    }

    for (int i = 0; i <= n; i++) {
        __syncthreads();
        if (i < n) {
            const int tile = bx + i * S;
            char* fp = smem + (i & 1) * 17408;
#pragma unroll
            for (int cc = 0; cc < 4; cc++) {
                uint4 hw;
                hw.x = cvt2h(v[cc][0].x, v[cc][0].y);
                hw.y = cvt2h(v[cc][0].z, v[cc][0].w);
                hw.z = cvt2h(v[cc][1].x, v[cc][1].y);
                hw.w = cvt2h(v[cc][1].z, v[cc][1].w);
                *reinterpret_cast<uint4*>(fp + (c0 + cc) * 272 + t8 * 2) = hw;
                *reinterpret_cast<uint4*>(xhb + (size_t)(c0 + cc) * N_TOK + tile * 128 + t8) = hw;
            }
            if (i + 1 < n) {
                const int tn = tile + S;
#pragma unroll
                for (int cc = 0; cc < 4; cc++) {
                    const float* p = xb + (size_t)(c0 + cc) * N_TOK + tn * 128 + t8;
                    v[cc][0] = *reinterpret_cast<const float4*>(p);
                    v[cc][1] = *reinterpret_cast<const float4*>(p + 4);
                }
            }
        }
        if (i > 0) {
            const uint32_t fb = sb + ((i - 1) & 1) * 17408;
#pragma unroll
            for (int k = 0; k < 4; k++) {
                uint32_t af[4];
                ldsm4(af, fb + aOff + k * 32);
#pragma unroll
                for (int nn2 = 0; nn2 < 4; nn2++) {
                    uint32_t bf[4];
                    ldsm4(bf, fb + bOff + nn2 * (16 * 272) + k * 32);
                    mma16816(d[2 * nn2],     af, bf[0], bf[2]);
                    mma16816(d[2 * nn2 + 1], af, bf[1], bf[3]);
                }
            }
        }
    }

    // epilogue: stage D (2 regions of float[64][68]), combine, one atomic each
    __syncthreads();
    float* sf = reinterpret_cast<float*>(smem) + kh * 4352;
    const int row0 = 16 * mw + (lane >> 2);
    const int col0 = 2 * (lane & 3);
#pragma unroll
    for (int nn = 0; nn < 8; nn++) {
        sf[row0 * 68 + 8 * nn + col0]           = d[nn][0];
        sf[row0 * 68 + 8 * nn + col0 + 1]       = d[nn][1];
        sf[(row0 + 8) * 68 + 8 * nn + col0]     = d[nn][2];
        sf[(row0 + 8) * 68 + 8 * nn + col0 + 1] = d[nn][3];
    }
    __syncthreads();

    float* Sb = g_S + b * 4096;
    float* sf0 = reinterpret_cast<float*>(smem);
#pragma unroll
    for (int kk = 0; kk < 16; kk++) {
        int e = kk * 256 + tid;
        int ii = e >> 6, j2 = e & 63;
        atomicAdd(&Sb[e], sf0[ii * 68 + j2] + sf0[4352 + ii * 68 + j2]);
    }
}

// ---------------------------------------------------------------------------
// Pass B: fold weights into M[o][c]. One block per (head, batch).
// ---------------------------------------------------------------------------
__global__ void __launch_bounds__(256) combine_kernel(const float* __restrict__ w_qkv,
                                                      const float* __restrict__ w_out) {
    __shared__ float sS[4096];
    __shared__ float sA[2048];
    __shared__ float sC[1024];
    __shared__ float sP[2048];
    const int b = blockIdx.y, h = blockIdx.x;
    const int tid = threadIdx.x;

    const float* Sb = g_S + b * 4096;
    for (int k = tid; k < 4096; k += 256) sS[k] = Sb[k];
    __syncthreads();

    const float* Wq = w_qkv + (h * 32) * 64;
    const float* Wk = w_qkv + (128 + h * 32) * 64;
    const float* Wv = w_qkv + (256 + h * 32) * 64;

    for (int e = tid; e < 2048; e += 256) {
        int ii = e >> 6, c = e & 63;
        float s = 0.0f;
        for (int c2 = 0; c2 < 64; c2++) s += Wk[ii * 64 + c2] * sS[c2 * 64 + c];
        sA[e] = s;
    }
    __syncthreads();

    const float coef = 0.17677669529663688f / 4096.0f;
    for (int e = tid; e < 1024; e += 256) {
        int ii = e >> 5, jj = e & 31;
        float s = 0.0f;
        for (int c = 0; c < 64; c++) s += sA[ii * 64 + c] * Wv[jj * 64 + c];
        sC[e] = s * coef;
    }
    __syncthreads();

    for (int e = tid; e < 2048; e += 256) {
        int jj = e >> 6, c = e & 63;
        float s = 0.0f;
        for (int ii = 0; ii < 32; ii++) s += sC[ii * 32 + jj] * Wq[ii * 64 + c];
        sP[e] = s;
    }
    __syncthreads();

    float* Mb = g_M + b * 4096;
    for (int e = tid; e < 4096; e += 256) {
        int o = e >> 6, c = e & 63;
        float s = 0.0f;
        for (int jj = 0; jj < 32; jj++) s += w_out[o * 128 + h * 32 + jj] * sP[jj * 64 + c];
        atomicAdd(&Mb[e], s);
    }
}

// ---------------------------------------------------------------------------
// meanfix: M'[o][c] = M[o][c] - mean_o M[o][c]  (f16 -> g_Mh),
//          b'[o] = b[o] - mean(b)               (-> g_Bp).
// Makes the channel-mean of z = M'x + b' exactly zero -> LN needs only E[z^2].
// ---------------------------------------------------------------------------
__global__ void meanfix_kernel(const float* __restrict__ b_out) {
    const int b = blockIdx.x, c = threadIdx.x;   // 64 threads
    const float* Mb = g_M + b * 4096;
    float s = 0.0f;
    for (int o = 0; o < 64; o++) s += Mb[o * 64 + c];
    const float mb = s * (1.0f / 64.0f);
    for (int o = 0; o < 64; o++)
        g_Mh[b * 4096 + o * 64 + c] = __float2half(Mb[o * 64 + c] - mb);
    if (b == 0) {
        float sb = 0.0f;
        for (int o = 0; o < 64; o++) sb += b_out[o];
        g_Bp[c] = b_out[c] - sb * (1.0f / 64.0f);
    }
}

// ---------------------------------------------------------------------------
// Pass C: z = M'16 · x16 + b', out = z * rsqrt(mean(z^2)+eps) * gain.
// Reads f16 x from g_xh (half the bytes, no convert). LDG.128 reg pipeline
// (16 regs), double-buffered f16 X tile, mma one tile behind -> 1 sync/tile.
// 3 blocks/SM. Warp owns 16 tokens; LN = Σz² + 3-shfl butterfly; STG.64 .cs.
// smem: M' @0 (9216), X0 @9216, X1 @26624, bias/gain @44032 = 44544 B.
// ---------------------------------------------------------------------------
#define A_X0 9216
#define A_X1 26624
#define A_BG 44032
#define APPLY_SMEM 44544

__global__ void __launch_bounds__(256, 3) apply_kernel(const float* __restrict__ gain,
                                                       float* __restrict__ out) {
    extern __shared__ char smem[];
    const uint32_t sb = smem_u32(smem);
    const int tid = threadIdx.x, wid = tid >> 5, lane = tid & 31;
    const int b = blockIdx.y;
    const __half* xhb = g_xh + (size_t)b * NCH * N_TOK;
    float* ob = out + (size_t)b * NCH * N_TOK;
    const int NT = N_TOK / 128, S = gridDim.x, bx = blockIdx.x;
    const int n = (NT - 1 - bx) / S + 1;

    // setup: M' f16 into smem (stride 72 halves), bias/gain tables
    for (int e = tid; e < 512; e += 256) {
        int o = e >> 3, c8 = (e & 7) * 8;
        uint4 w = *reinterpret_cast<const uint4*>(g_Mh + b * 4096 + o * 64 + c8);
        *reinterpret_cast<uint4*>(smem + o * 144 + c8 * 2) = w;
    }
    if (tid < 64) {
        reinterpret_cast<float*>(smem + A_BG)[tid]       = g_Bp[tid];
        reinterpret_cast<float*>(smem + A_BG + 256)[tid] = gain[tid];
    }

    const int row = lane >> 2;
    const int tw  = 16 * wid;
    const uint32_t xOff = ((lane & 7) + ((lane >> 4) << 3)) * 272 +
                          (tw + ((lane >> 3) & 1) * 8) * 2;
    const uint32_t aBa = sb + (lane & 15) * 144 + ((lane >> 4) & 1) * 16;
    const float* sbias = reinterpret_cast<const float*>(smem + A_BG);
    const float* sgain = reinterpret_cast<const float*>(smem + A_BG + 256);

    // prologue: LDG tile 0 (f16, 4 x uint4)
    uint4 v[4];
#pragma unroll
    for (int k = 0; k < 4; k++) {
        int idx = k * 256 + tid;
        int c = idx >> 4, t8 = (idx & 15) * 8;
        v[k] = *reinterpret_cast<const uint4*>(xhb + (size_t)c * N_TOK + bx * 128 + t8);
    }

    for (int i = 0; i <= n; i++) {
        __syncthreads();
        if (i < n) {
            char* fp = smem + A_X0 + (i & 1) * 17408;
#pragma unroll
            for (int k = 0; k < 4; k++) {
                int idx = k * 256 + tid;
                int c = idx >> 4, t8 = (idx & 15) * 8;
                *reinterpret_cast<uint4*>(fp + c * 272 + t8 * 2) = v[k];
            }
            if (i + 1 < n) {
                const int tn = bx + (i + 1) * S;
#pragma unroll
                for (int k = 0; k < 4; k++) {
                    int idx = k * 256 + tid;
                    int c = idx >> 4, t8 = (idx & 15) * 8;
                    v[k] = *reinterpret_cast<const uint4*>(xhb + (size_t)c * N_TOK + tn * 128 + t8);
                }
            }
        }
        if (i > 0) {
            const int tile = bx + (i - 1) * S;
            const uint32_t xTB = sb + A_X0 + ((i - 1) & 1) * 17408 + xOff;

            float d[4][2][4];
#pragma unroll
            for (int m = 0; m < 4; m++)
#pragma unroll
                for (int nn = 0; nn < 2; nn++)
#pragma unroll
                    for (int r = 0; r < 4; r++) d[m][nn][r] = 0.0f;

#pragma unroll
            for (int kp = 0; kp < 4; kp++) {
                uint32_t bh[4];
                ldsm4t(bh, xTB + kp * 4352);
#pragma unroll
                for (int m = 0; m < 4; m++) {
                    uint32_t af[4];
                    ldsm4(af, aBa + m * 2304 + kp * 32);
                    mma16816(d[m][0], af, bh[0], bh[2]);
                    mma16816(d[m][1], af, bh[1], bh[3]);
                }
            }

            // epilogue: z = d + b', qq = sum z^2, butterfly, scale, store
            float bbv[4][2], ggv[4][2];
#pragma unroll
            for (int m = 0; m < 4; m++)
#pragma unroll
                for (int rh = 0; rh < 2; rh++) {
                    int o = 16 * m + row + 8 * rh;
                    bbv[m][rh] = sbias[o];
                    ggv[m][rh] = sgain[o];
                }

            float qq[2][2] = {{0.f, 0.f}, {0.f, 0.f}};
#pragma unroll
            for (int m = 0; m < 4; m++)
#pragma unroll
                for (int nn = 0; nn < 2; nn++)
#pragma unroll
                    for (int r = 0; r < 4; r++) {
                        float z = d[m][nn][r] + bbv[m][r >> 1];
                        d[m][nn][r] = z;
                        qq[nn][r & 1] += z * z;
                    }
#pragma unroll
            for (int mask = 4; mask < 32; mask <<= 1)
#pragma unroll
                for (int nn = 0; nn < 2; nn++)
#pragma unroll
                    for (int p = 0; p < 2; p++)
                        qq[nn][p] += __shfl_xor_sync(0xffffffffu, qq[nn][p], mask);
            float istd[2][2];
#pragma unroll
            for (int nn = 0; nn < 2; nn++)
#pragma unroll
                for (int p = 0; p < 2; p++)
                    istd[nn][p] = rsqrtf(qq[nn][p] * (1.0f / 64.0f) + 1e-5f);

            float* obp = ob + (size_t)tile * 128;
#pragma unroll
            for (int m = 0; m < 4; m++)
#pragma unroll
                for (int nn = 0; nn < 2; nn++) {
                    const int o  = 16 * m + row;
                    const int tt = tw + 8 * nn + 2 * (lane & 3);
                    stcs2(obp + (size_t)o * N_TOK + tt,
                          d[m][nn][0] * istd[nn][0] * ggv[m][0],
                          d[m][nn][1] * istd[nn][1] * ggv[m][0]);
                    stcs2(obp + (size_t)(o + 8) * N_TOK + tt,
                          d[m][nn][2] * istd[nn][0] * ggv[m][1],
                          d[m][nn][3] * istd[nn][1] * ggv[m][1]);
                }
        }
    }
}

// ---------------------------------------------------------------------------
extern "C" void kernel_launch(void* const* d_in, const int* in_sizes, int n_in,
                              void* d_out, int out_size) {
    const float* x     = (const float*)d_in[0];
    const float* w_qkv = (const float*)d_in[1];
    const float* w_out = (const float*)d_in[2];
    const float* b_out = (const float*)d_in[3];
    const float* g     = (const float*)d_in[4];
    float* out = (float*)d_out;

    cudaFuncSetAttribute(gram_kernel,  cudaFuncAttributeMaxDynamicSharedMemorySize, GRAM_SMEM);
    cudaFuncSetAttribute(apply_kernel, cudaFuncAttributeMaxDynamicSharedMemorySize, APPLY_SMEM);

    zero_kernel<<<32, 256>>>();
    gram_kernel<<<dim3(148, 2), 256, GRAM_SMEM>>>(x);
    combine_kernel<<<dim3(4, 2), 256>>>(w_qkv, w_out);
    meanfix_kernel<<<2, 64>>>(b_out);
    apply_kernel<<<dim3(222, 2), 256, APPLY_SMEM>>>(g, out);
}

// round 12
// speedup vs baseline: 1.0491x; 1.0491x over previous
#include <cuda_runtime.h>
#include <cuda_fp16.h>
#include <cstdint>

#define N_TOK 262144
#define NCH   64

__device__ float  g_S [2 * 4096];
__device__ float  g_M [2 * 4096];    // M: [o][c]
__device__ __half g_xh[(size_t)2 * NCH * N_TOK];   // f16 x cache (64MB)

// ---------------------------------------------------------------------------
static __device__ __forceinline__ uint32_t smem_u32(const void* p) {
    uint32_t a;
    asm("{ .reg .u64 t; cvta.to.shared.u64 t, %1; cvt.u32.u64 %0, t; }" : "=r"(a) : "l"(p));
    return a;
}
static __device__ __forceinline__ void ldsm4(uint32_t (&r)[4], uint32_t a) {
    asm volatile("ldmatrix.sync.aligned.m8n8.x4.shared.b16 {%0,%1,%2,%3}, [%4];"
                 : "=r"(r[0]), "=r"(r[1]), "=r"(r[2]), "=r"(r[3]) : "r"(a));
}
static __device__ __forceinline__ void ldsm4t(uint32_t (&r)[4], uint32_t a) {
    asm volatile("ldmatrix.sync.aligned.m8n8.x4.trans.shared.b16 {%0,%1,%2,%3}, [%4];"
                 : "=r"(r[0]), "=r"(r[1]), "=r"(r[2]), "=r"(r[3]) : "r"(a));
}
static __device__ __forceinline__ void mma16816(float (&d)[4], const uint32_t (&a)[4],
                                                uint32_t b0, uint32_t b1) {
    asm volatile("mma.sync.aligned.m16n8k16.row.col.f32.f16.f16.f32 "
                 "{%0,%1,%2,%3},{%4,%5,%6,%7},{%8,%9},{%0,%1,%2,%3};"
                 : "+f"(d[0]), "+f"(d[1]), "+f"(d[2]), "+f"(d[3])
                 : "r"(a[0]), "r"(a[1]), "r"(a[2]), "r"(a[3]), "r"(b0), "r"(b1));
}
static __device__ __forceinline__ uint32_t cvt2h(float lo, float hi) {
    uint32_t d;
    asm("cvt.rn.f16x2.f32 %0,%1,%2;" : "=r"(d) : "f"(hi), "f"(lo));
    return d;
}
static __device__ __forceinline__ void stcs2(float* p, float a, float b) {
    asm volatile("st.global.cs.v2.f32 [%0], {%1,%2};" :: "l"(p), "f"(a), "f"(b) : "memory");
}
static __device__ __forceinline__ void cp16(uint32_t dst, const void* src) {
    asm volatile("cp.async.cg.shared.global [%0], [%1], 16;" :: "r"(dst), "l"(src));
}
#define CP_COMMIT() asm volatile("cp.async.commit_group;" ::: "memory")
#define CP_WAIT2()  asm volatile("cp.async.wait_group 2;" ::: "memory")

// ---------------------------------------------------------------------------
__global__ void zero_kernel() {
    int i = blockIdx.x * 256 + threadIdx.x;
    if (i < 2 * 4096) { g_S[i] = 0.0f; g_M[i] = 0.0f; }
}

// ---------------------------------------------------------------------------
// Pass A: S = X16·X16^T, and write f16 x to g_xh.
// 128-tok tiles; LDG.128 reg pipeline (1 tile ahead), double-buffered f16
// smem tile [64 ch][272B], mma one tile behind -> ONE sync per tile.
// ---------------------------------------------------------------------------
#define GRAM_SMEM 34816

__global__ void __launch_bounds__(256, 2) gram_kernel(const float* __restrict__ x) {
    extern __shared__ char smem[];
    const uint32_t sb = smem_u32(smem);
    const int tid = threadIdx.x, wid = tid >> 5, lane = tid & 31;
    const int b = blockIdx.y;
    const float* xb = x + (size_t)b * NCH * N_TOK;
    __half* xhb = g_xh + (size_t)b * NCH * N_TOK;
    const int mw = wid & 3, kh = wid >> 2;
    const int NT = N_TOK / 128, S = gridDim.x, bx = blockIdx.x;
    const int n = (NT - 1 - bx) / S + 1;

    float d[8][4];
#pragma unroll
    for (int nn = 0; nn < 8; nn++)
#pragma unroll
        for (int r = 0; r < 4; r++) d[nn][r] = 0.0f;

    const int c0 = (tid >> 4) * 4;
    const int t8 = (tid & 15) * 8;
    const uint32_t aOff = (16 * mw + (lane & 15)) * 272 + ((lane >> 4) & 1) * 16 + kh * 128;
    const uint32_t bOff = (lane & 15) * 272 + ((lane >> 4) & 1) * 16 + kh * 128;

    float4 v[4][2];
#pragma unroll
    for (int cc = 0; cc < 4; cc++) {
        const float* p = xb + (size_t)(c0 + cc) * N_TOK + bx * 128 + t8;
        v[cc][0] = *reinterpret_cast<const float4*>(p);
        v[cc][1] = *reinterpret_cast<const float4*>(p + 4);
    }

    for (int i = 0; i <= n; i++) {
        __syncthreads();
        if (i < n) {
            const int tile = bx + i * S;
            char* fp = smem + (i & 1) * 17408;
#pragma unroll
            for (int cc = 0; cc < 4; cc++) {
                uint4 hw;
                hw.x = cvt2h(v[cc][0].x, v[cc][0].y);
                hw.y = cvt2h(v[cc][0].z, v[cc][0].w);
                hw.z = cvt2h(v[cc][1].x, v[cc][1].y);
                hw.w = cvt2h(v[cc][1].z, v[cc][1].w);
                *reinterpret_cast<uint4*>(fp + (c0 + cc) * 272 + t8 * 2) = hw;
                *reinterpret_cast<uint4*>(xhb + (size_t)(c0 + cc) * N_TOK + tile * 128 + t8) = hw;
            }
            if (i + 1 < n) {
                const int tn = tile + S;
#pragma unroll
                for (int cc = 0; cc < 4; cc++) {
                    const float* p = xb + (size_t)(c0 + cc) * N_TOK + tn * 128 + t8;
                    v[cc][0] = *reinterpret_cast<const float4*>(p);
                    v[cc][1] = *reinterpret_cast<const float4*>(p + 4);
                }
            }
        }
        if (i > 0) {
            const uint32_t fb = sb + ((i - 1) & 1) * 17408;
#pragma unroll
            for (int k = 0; k < 4; k++) {
                uint32_t af[4];
                ldsm4(af, fb + aOff + k * 32);
#pragma unroll
                for (int nn2 = 0; nn2 < 4; nn2++) {
                    uint32_t bf[4];
                    ldsm4(bf, fb + bOff + nn2 * (16 * 272) + k * 32);
                    mma16816(d[2 * nn2],     af, bf[0], bf[2]);
                    mma16816(d[2 * nn2 + 1], af, bf[1], bf[3]);
                }
            }
        }
    }

    __syncthreads();
    float* sf = reinterpret_cast<float*>(smem) + kh * 4352;
    const int row0 = 16 * mw + (lane >> 2);
    const int col0 = 2 * (lane & 3);
#pragma unroll
    for (int nn = 0; nn < 8; nn++) {
        sf[row0 * 68 + 8 * nn + col0]           = d[nn][0];
        sf[row0 * 68 + 8 * nn + col0 + 1]       = d[nn][1];
        sf[(row0 + 8) * 68 + 8 * nn + col0]     = d[nn][2];
        sf[(row0 + 8) * 68 + 8 * nn + col0 + 1] = d[nn][3];
    }
    __syncthreads();

    float* Sb = g_S + b * 4096;
    float* sf0 = reinterpret_cast<float*>(smem);
#pragma unroll
    for (int kk = 0; kk < 16; kk++) {
        int e = kk * 256 + tid;
        int ii = e >> 6, j2 = e & 63;
        atomicAdd(&Sb[e], sf0[ii * 68 + j2] + sf0[4352 + ii * 68 + j2]);
    }
}

// ---------------------------------------------------------------------------
// Pass B: fold weights into M[o][c]. One block per (head, batch).
// ---------------------------------------------------------------------------
__global__ void __launch_bounds__(256) combine_kernel(const float* __restrict__ w_qkv,
                                                      const float* __restrict__ w_out) {
    __shared__ float sS[4096];
    __shared__ float sA[2048];
    __shared__ float sC[1024];
    __shared__ float sP[2048];
    const int b = blockIdx.y, h = blockIdx.x;
    const int tid = threadIdx.x;

    const float* Sb = g_S + b * 4096;
    for (int k = tid; k < 4096; k += 256) sS[k] = Sb[k];
    __syncthreads();

    const float* Wq = w_qkv + (h * 32) * 64;
    const float* Wk = w_qkv + (128 + h * 32) * 64;
    const float* Wv = w_qkv + (256 + h * 32) * 64;

    for (int e = tid; e < 2048; e += 256) {
        int ii = e >> 6, c = e & 63;
        float s = 0.0f;
        for (int c2 = 0; c2 < 64; c2++) s += Wk[ii * 64 + c2] * sS[c2 * 64 + c];
        sA[e] = s;
    }
    __syncthreads();

    const float coef = 0.17677669529663688f / 4096.0f;
    for (int e = tid; e < 1024; e += 256) {
        int ii = e >> 5, jj = e & 31;
        float s = 0.0f;
        for (int c = 0; c < 64; c++) s += sA[ii * 64 + c] * Wv[jj * 64 + c];
        sC[e] = s * coef;
    }
    __syncthreads();

    for (int e = tid; e < 2048; e += 256) {
        int jj = e >> 6, c = e & 63;
        float s = 0.0f;
        for (int ii = 0; ii < 32; ii++) s += sC[ii * 32 + jj] * Wq[ii * 64 + c];
        sP[e] = s;
    }
    __syncthreads();

    float* Mb = g_M + b * 4096;
    for (int e = tid; e < 4096; e += 256) {
        int o = e >> 6, c = e & 63;
        float s = 0.0f;
        for (int jj = 0; jj < 32; jj++) s += w_out[o * 128 + h * 32 + jj] * sP[jj * 64 + c];
        atomicAdd(&Mb[e], s);
    }
}

// ---------------------------------------------------------------------------
// Pass C: z = M'16·x16 + b', out = z * rsqrt(mean(z^2)+eps) * gain.
// M' (mean-free) derived IN-BLOCK from g_M (16KB broadcast read) — no
// separate meanfix kernel. x read as f16 from g_xh via cp.async, 3-stage,
// directly into ldmatrix-ready tiles (no registers, no conversion).
// Warp owns 16 tokens; LN = Σz² + butterfly; STG.64 .cs.
// smem: M' @0 (9216), X[3] @9216 (3x17408), bias/gain/cm @61440 = 62208 B.
// ---------------------------------------------------------------------------
#define A_X  9216
#define A_BG 61440
#define APPLY_SMEM 62208

__global__ void __launch_bounds__(256, 3) apply_kernel(const float* __restrict__ b_out,
                                                       const float* __restrict__ gain,
                                                       float* __restrict__ out) {
    extern __shared__ char smem[];
    const uint32_t sb = smem_u32(smem);
    const int tid = threadIdx.x, wid = tid >> 5, lane = tid & 31;
    const int b = blockIdx.y;
    const __half* xhb = g_xh + (size_t)b * NCH * N_TOK;
    float* ob = out + (size_t)b * NCH * N_TOK;
    const int NT = N_TOK / 128, S = gridDim.x, bx = blockIdx.x;
    const int n = (NT - 1 - bx) / S + 1;

    // ---- setup: mean-free M' + b' (uses X buffer 0 as fp32 scratch) ----
    float* Mt = reinterpret_cast<float*>(smem + A_X);
#pragma unroll
    for (int k = 0; k < 4; k++) {
        int idx = k * 256 + tid;
        reinterpret_cast<float4*>(Mt)[idx] =
            reinterpret_cast<const float4*>(g_M + b * 4096)[idx];
    }
    __syncthreads();
    if (tid < 64) {
        float s = 0.0f;
        for (int o = 0; o < 64; o++) s += Mt[o * 64 + tid];
        reinterpret_cast<float*>(smem + A_BG + 512)[tid] = s * (1.0f / 64.0f);
        float bs = 0.0f;
        for (int o = 0; o < 64; o++) bs += b_out[o];
        reinterpret_cast<float*>(smem + A_BG)[tid]       = b_out[tid] - bs * (1.0f / 64.0f);
        reinterpret_cast<float*>(smem + A_BG + 256)[tid] = gain[tid];
    }
    __syncthreads();
    {
        const float* cm = reinterpret_cast<const float*>(smem + A_BG + 512);
        __half* pa = reinterpret_cast<__half*>(smem);
#pragma unroll
        for (int k = 0; k < 16; k++) {
            int e = k * 256 + tid;
            int o = e >> 6, c = e & 63;
            pa[o * 72 + c] = __float2half(Mt[e] - cm[c]);
        }
    }
    __syncthreads();

    // ---- prologue: 3 cp.async stages of f16 x tiles ----
    const int cL = tid >> 4;           // channel for cp (0..15 x16 pattern)
    const int tL = (tid & 15) * 8;     // 8 tokens (16B)
#pragma unroll
    for (int s2 = 0; s2 < 3; s2++) {
        int tt = bx + s2 * S;
        if (s2 < n) {
#pragma unroll
            for (int k = 0; k < 4; k++) {
                int c = cL + k * 16;
                cp16(sb + A_X + s2 * 17408 + c * 272 + tL * 2,
                     xhb + (size_t)c * N_TOK + tt * 128 + tL);
            }
        }
        CP_COMMIT();
    }

    const int row = lane >> 2;
    const int tw  = 16 * wid;
    const uint32_t xOff = ((lane & 7) + ((lane >> 4) << 3)) * 272 +
                          (tw + ((lane >> 3) & 1) * 8) * 2;
    const uint32_t aBa = sb + (lane & 15) * 144 + ((lane >> 4) & 1) * 16;
    const float* sbias = reinterpret_cast<const float*>(smem + A_BG);
    const float* sgain = reinterpret_cast<const float*>(smem + A_BG + 256);

    int bufi = 0;
    for (int i = 0; i < n; i++, bufi = (bufi == 2) ? 0 : bufi + 1) {
        CP_WAIT2();
        __syncthreads();
        const int tile = bx + i * S;
        const uint32_t xTB = sb + A_X + bufi * 17408 + xOff;

        float d[4][2][4];
#pragma unroll
        for (int m = 0; m < 4; m++)
#pragma unroll
            for (int nn = 0; nn < 2; nn++)
#pragma unroll
                for (int r = 0; r < 4; r++) d[m][nn][r] = 0.0f;

#pragma unroll
        for (int kp = 0; kp < 4; kp++) {
            uint32_t bh[4];
            ldsm4t(bh, xTB + kp * 4352);
#pragma unroll
            for (int m = 0; m < 4; m++) {
                uint32_t af[4];
                ldsm4(af, aBa + m * 2304 + kp * 32);
                mma16816(d[m][0], af, bh[0], bh[2]);
                mma16816(d[m][1], af, bh[1], bh[3]);
            }
        }

        // epilogue: z = d + b', Σz², butterfly, scale, store
        float bbv[4][2], ggv[4][2];
#pragma unroll
        for (int m = 0; m < 4; m++)
#pragma unroll
            for (int rh = 0; rh < 2; rh++) {
                int o = 16 * m + row + 8 * rh;
                bbv[m][rh] = sbias[o];
                ggv[m][rh] = sgain[o];
            }
        float qq[2][2] = {{0.f, 0.f}, {0.f, 0.f}};
#pragma unroll
        for (int m = 0; m < 4; m++)
#pragma unroll
            for (int nn = 0; nn < 2; nn++)
#pragma unroll
                for (int r = 0; r < 4; r++) {
                    float z = d[m][nn][r] + bbv[m][r >> 1];
                    d[m][nn][r] = z;
                    qq[nn][r & 1] += z * z;
                }
#pragma unroll
        for (int mask = 4; mask < 32; mask <<= 1)
#pragma unroll
            for (int nn = 0; nn < 2; nn++)
#pragma unroll
                for (int p = 0; p < 2; p++)
                    qq[nn][p] += __shfl_xor_sync(0xffffffffu, qq[nn][p], mask);
        float istd[2][2];
#pragma unroll
        for (int nn = 0; nn < 2; nn++)
#pragma unroll
            for (int p = 0; p < 2; p++)
                istd[nn][p] = rsqrtf(qq[nn][p] * (1.0f / 64.0f) + 1e-5f);

        float* obp = ob + (size_t)tile * 128;
#pragma unroll
        for (int m = 0; m < 4; m++)
#pragma unroll
            for (int nn = 0; nn < 2; nn++) {
                const int o  = 16 * m + row;
                const int tt = tw + 8 * nn + 2 * (lane & 3);
                stcs2(obp + (size_t)o * N_TOK + tt,
                      d[m][nn][0] * istd[nn][0] * ggv[m][0],
                      d[m][nn][1] * istd[nn][1] * ggv[m][0]);
                stcs2(obp + (size_t)(o + 8) * N_TOK + tt,
                      d[m][nn][2] * istd[nn][0] * ggv[m][1],
                      d[m][nn][3] * istd[nn][1] * ggv[m][1]);
            }

        __syncthreads();   // all reads of buf done before refill
        {
            int pf = i + 3;
            if (pf < n) {
                int tt = bx + pf * S;
#pragma unroll
                for (int k = 0; k < 4; k++) {
                    int c = cL + k * 16;
                    cp16(sb + A_X + bufi * 17408 + c * 272 + tL * 2,
                         xhb + (size_t)c * N_TOK + tt * 128 + tL);
                }
            }
            CP_COMMIT();
        }
    }
}

// ---------------------------------------------------------------------------
extern "C" void kernel_launch(void* const* d_in, const int* in_sizes, int n_in,
                              void* d_out, int out_size) {
    const float* x     = (const float*)d_in[0];
    const float* w_qkv = (const float*)d_in[1];
    const float* w_out = (const float*)d_in[2];
    const float* b_out = (const float*)d_in[3];
    const float* g     = (const float*)d_in[4];
    float* out = (float*)d_out;

    cudaFuncSetAttribute(gram_kernel,  cudaFuncAttributeMaxDynamicSharedMemorySize, GRAM_SMEM);
    cudaFuncSetAttribute(apply_kernel, cudaFuncAttributeMaxDynamicSharedMemorySize, APPLY_SMEM);

    zero_kernel<<<32, 256>>>();
    gram_kernel<<<dim3(148, 2), 256, GRAM_SMEM>>>(x);
    combine_kernel<<<dim3(4, 2), 256>>>(w_qkv, w_out);
    apply_kernel<<<dim3(222, 2), 256, APPLY_SMEM>>>(b_out, g, out);
}